// round 3
// baseline (speedup 1.0000x reference)
#include <cuda_runtime.h>
#include <cstdint>
#include <cstddef>

// ---------------------------------------------------------------------------
// MultiheadedAttention2 (batch-axis softmax quirk) — tf32 mma.sync v3:
//   * all operands pre-rounded to exact tf32 (cvt.rna) -> no cvt in inner loop
//   * K permuted within 32-groups in GLOBAL layout: pos(k)=(k&3)*8+(k>>2)
//     -> fragments load as LDS.128 (24 per warp-tile instead of 96 scalar LDS)
//   * all GEMMs TRANS_B (V transposed once); 4-stage cp.async pipeline
//   * producers of GEMM inputs emit rounded+permuted outputs (smem-staged
//     epilogue / softmax / transpose), so consumers need zero fixup.
// ---------------------------------------------------------------------------

#define B_SZ 8
#define T_SZ 2048
#define E_SZ 512
#define HE_SZ 4096
#define SCALE_F 0.04419417382415922f  // 512^-0.5

#define STAGES 4
#define STAGE_FLOATS 9216          // A: 128*36 + B: 128*36
#define SMEM_BYTES (STAGES * STAGE_FLOATS * 4)  // 147456

// Scratch (device globals; allocation-free rule)
__device__ float g_q[(size_t)B_SZ * T_SZ * HE_SZ];     // rounded+permuted(HE)
__device__ float g_k[(size_t)B_SZ * T_SZ * HE_SZ];     // rounded+permuted(HE)
__device__ float g_v[(size_t)B_SZ * T_SZ * HE_SZ];     // plain fp32
__device__ float g_vT[(size_t)B_SZ * HE_SZ * T_SZ];    // rounded+permuted(T)
__device__ float g_att[(size_t)B_SZ * T_SZ * T_SZ];    // logits then att (r+p)
__device__ float g_att2[(size_t)B_SZ * T_SZ * HE_SZ];  // rounded+permuted(HE)
__device__ float g_rkey[(size_t)B_SZ * T_SZ * E_SZ];
__device__ float g_rqry[(size_t)B_SZ * T_SZ * E_SZ];
__device__ float g_rval[(size_t)B_SZ * T_SZ * E_SZ];
__device__ float g_rWk[(size_t)HE_SZ * E_SZ];
__device__ float g_rWq[(size_t)HE_SZ * E_SZ];
__device__ float g_rWv[(size_t)HE_SZ * E_SZ];
__device__ float g_rWo[(size_t)E_SZ * HE_SZ];

static __device__ __forceinline__ float f2tf32f(float x) {
    uint32_t u;
    asm volatile("cvt.rna.tf32.f32 %0, %1;" : "=r"(u) : "f"(x));
    return __uint_as_float(u);
}

static __device__ __forceinline__ void mma_tf32(float* c, const float* a, const float* b) {
    asm volatile(
        "mma.sync.aligned.m16n8k8.row.col.f32.tf32.tf32.f32 "
        "{%0,%1,%2,%3}, {%4,%5,%6,%7}, {%8,%9}, {%0,%1,%2,%3};\n"
        : "+f"(c[0]), "+f"(c[1]), "+f"(c[2]), "+f"(c[3])
        : "r"(__float_as_uint(a[0])), "r"(__float_as_uint(a[1])),
          "r"(__float_as_uint(a[2])), "r"(__float_as_uint(a[3])),
          "r"(__float_as_uint(b[0])), "r"(__float_as_uint(b[1])));
}

static __device__ __forceinline__ void cp_async16(float* smem_dst, const float* gptr) {
    uint32_t s = (uint32_t)__cvta_generic_to_shared(smem_dst);
    asm volatile("cp.async.cg.shared.global [%0], [%1], 16;\n" :: "r"(s), "l"(gptr));
}
static __device__ __forceinline__ void cp_commit() {
    asm volatile("cp.async.commit_group;\n");
}
template <int N>
static __device__ __forceinline__ void cp_wait() {
    asm volatile("cp.async.wait_group %0;\n" :: "n"(N));
}

// ---------------------------------------------------------------------------
// GEMM: C[M,N] = alpha * A @ B^T (+ bias). A [M,K], B [N,K], both row-major and
// ALREADY rounded to tf32 + K-permuted within 32-groups.
// PERM_OUT: C written rounded to tf32 and N-permuted (feeds a later GEMM).
// ---------------------------------------------------------------------------
template <bool PERM_OUT, bool HAS_BIAS>
__global__ __launch_bounds__(256, 1)
void gemm_tf32(const float* __restrict__ A, const float* __restrict__ Bm,
               const float* __restrict__ bias, float* __restrict__ C,
               int M, int N, int K, float alpha,
               long long sA, long long sB, long long sC)
{
    extern __shared__ float smem[];

    const float* Ab = A + (long long)blockIdx.z * sA;
    const float* Bb = Bm + (long long)blockIdx.z * sB;
    float* Cb = C + (long long)blockIdx.z * sC;

    const int bm = blockIdx.y * 128;
    const int bn = blockIdx.x * 128;
    const int tid = threadIdx.x;
    const int lane = tid & 31;
    const int warp = tid >> 5;
    const int wm = (warp & 3) * 32;   // 4 warps down M
    const int wn = (warp >> 2) * 64;  // 2 warps across N
    const int gr = lane >> 2;         // 0..7
    const int gc = lane & 3;          // 0..3

    float acc[2][8][4];
#pragma unroll
    for (int i = 0; i < 2; ++i)
#pragma unroll
        for (int j = 0; j < 8; ++j)
#pragma unroll
            for (int r = 0; r < 4; ++r) acc[i][j][r] = 0.f;

    const int ldrow = tid >> 3;        // 0..31
    const int ldcol = (tid & 7) << 2;  // 0..28

    const int nk = K >> 5;

    auto load_tile = [&](int kt, int stage) {
        float* sA = smem + stage * STAGE_FLOATS;
        float* sB = sA + 4608;
        const int k0g = kt << 5;
#pragma unroll
        for (int p = 0; p < 4; ++p) {
            const int r = ldrow + p * 32;
            cp_async16(sA + r * 36 + ldcol, Ab + (size_t)(bm + r) * K + (k0g + ldcol));
            cp_async16(sB + r * 36 + ldcol, Bb + (size_t)(bn + r) * K + (k0g + ldcol));
        }
    };

#pragma unroll
    for (int s = 0; s < STAGES - 1; ++s) {
        if (s < nk) load_tile(s, s);
        cp_commit();
    }

    for (int kt = 0; kt < nk; ++kt) {
        const int stage = kt & (STAGES - 1);
        cp_wait<STAGES - 2>();
        __syncthreads();

        const int pf = kt + STAGES - 1;
        if (pf < nk) load_tile(pf, pf & (STAGES - 1));
        cp_commit();

        const float* sA = smem + stage * STAGE_FLOATS;
        const float* sB = sA + 4608;

        // Permuted layout: float4 at [row][gc*8 + h*4] holds k = 16h + {0,4,8,12} + gc
#pragma unroll
        for (int h = 0; h < 2; ++h) {
            float4 av[2][2];
#pragma unroll
            for (int i = 0; i < 2; ++i) {
                const int r = wm + i * 16 + gr;
                av[i][0] = *reinterpret_cast<const float4*>(sA + (size_t)r * 36 + gc * 8 + h * 4);
                av[i][1] = *reinterpret_cast<const float4*>(sA + (size_t)(r + 8) * 36 + gc * 8 + h * 4);
            }
            float4 bv[8];
#pragma unroll
            for (int j = 0; j < 8; ++j) {
                const int cn = wn + j * 8 + gr;
                bv[j] = *reinterpret_cast<const float4*>(sB + (size_t)cn * 36 + gc * 8 + h * 4);
            }
#pragma unroll
            for (int i = 0; i < 2; ++i) {
                const float alo[4] = {av[i][0].x, av[i][1].x, av[i][0].y, av[i][1].y};
                const float ahi[4] = {av[i][0].z, av[i][1].z, av[i][0].w, av[i][1].w};
#pragma unroll
                for (int j = 0; j < 8; ++j) {
                    const float blo[2] = {bv[j].x, bv[j].y};
                    mma_tf32(acc[i][j], alo, blo);
                }
#pragma unroll
                for (int j = 0; j < 8; ++j) {
                    const float bhi[2] = {bv[j].z, bv[j].w};
                    mma_tf32(acc[i][j], ahi, bhi);
                }
            }
        }
        __syncthreads();
    }

    if (PERM_OUT) {
        // Stage C tile in smem, then emit rounded + N-permuted coalesced float4s.
        __syncthreads();
        float* cs = smem;  // [128][132]
#pragma unroll
        for (int i = 0; i < 2; ++i) {
#pragma unroll
            for (int j = 0; j < 8; ++j) {
                const int r = wm + i * 16 + gr;
                const int c = wn + j * 8 + gc * 2;
                float v0 = acc[i][j][0] * alpha;
                float v1 = acc[i][j][1] * alpha;
                float v2 = acc[i][j][2] * alpha;
                float v3 = acc[i][j][3] * alpha;
                if (HAS_BIAS) {
                    const float b0 = bias[bn + c], b1 = bias[bn + c + 1];
                    v0 += b0; v1 += b1; v2 += b0; v3 += b1;
                }
                cs[(size_t)r * 132 + c] = v0;
                cs[(size_t)r * 132 + c + 1] = v1;
                cs[(size_t)(r + 8) * 132 + c] = v2;
                cs[(size_t)(r + 8) * 132 + c + 1] = v3;
            }
        }
        __syncthreads();
        const int orow = tid >> 1;
        const int ohalf = tid & 1;
#pragma unroll
        for (int f = 0; f < 16; ++f) {
            const int colb = ohalf * 4 + f * 8;       // permuted output col base
            const int g = colb >> 5;
            // src col within group for output pos p+e: ((p&7)+e)*4 + (p>>3)
            const int srcbase = g * 32 + ohalf * 16 + (f & 3);
            float4 o;
            o.x = f2tf32f(cs[(size_t)orow * 132 + srcbase]);
            o.y = f2tf32f(cs[(size_t)orow * 132 + srcbase + 4]);
            o.z = f2tf32f(cs[(size_t)orow * 132 + srcbase + 8]);
            o.w = f2tf32f(cs[(size_t)orow * 132 + srcbase + 12]);
            *reinterpret_cast<float4*>(Cb + (size_t)(bm + orow) * N + bn + colb) = o;
        }
    } else {
#pragma unroll
        for (int i = 0; i < 2; ++i) {
#pragma unroll
            for (int j = 0; j < 8; ++j) {
                const int row = bm + wm + i * 16 + gr;
                const int col = bn + wn + j * 8 + gc * 2;
                float v0 = acc[i][j][0] * alpha;
                float v1 = acc[i][j][1] * alpha;
                float v2 = acc[i][j][2] * alpha;
                float v3 = acc[i][j][3] * alpha;
                if (HAS_BIAS) {
                    const float b0 = bias[col], b1 = bias[col + 1];
                    v0 += b0; v1 += b1; v2 += b0; v3 += b1;
                }
                Cb[(size_t)row * N + col] = v0;
                Cb[(size_t)row * N + col + 1] = v1;
                Cb[(size_t)(row + 8) * N + col] = v2;
                Cb[(size_t)(row + 8) * N + col + 1] = v3;
            }
        }
    }
}

// Round to tf32 + permute K within 32-groups. Flat layout; row lengths are
// multiples of 32 so groups never straddle rows.  out[base+p] = rna(in[base+invp(p)])
__global__ void round_perm(const float* __restrict__ in, float* __restrict__ out, long long n4)
{
    const long long i = (long long)blockIdx.x * blockDim.x + threadIdx.x;
    if (i >= n4) return;
    const long long q = i * 4;
    const long long base = q & ~31LL;
    const int p = (int)(q & 31);
    const int src = (p & 7) * 4 + (p >> 3);
    float4 o;
    o.x = f2tf32f(in[base + src]);
    o.y = f2tf32f(in[base + src + 4]);
    o.z = f2tf32f(in[base + src + 8]);
    o.w = f2tf32f(in[base + src + 12]);
    *reinterpret_cast<float4*>(out + q) = o;
}

// Softmax across batch axis (8 entries), output rounded + s-permuted.
__global__ void softmax_b8(float* __restrict__ d, int plane)
{
    const int i = blockIdx.x * blockDim.x + threadIdx.x;  // float4 index
    if (i >= plane / 4) return;
    const int s = i * 4;
    float4 v[B_SZ];
    float4 m = make_float4(-1e30f, -1e30f, -1e30f, -1e30f);
#pragma unroll
    for (int b = 0; b < B_SZ; ++b) {
        v[b] = *reinterpret_cast<const float4*>(d + (size_t)b * plane + s);
        m.x = fmaxf(m.x, v[b].x); m.y = fmaxf(m.y, v[b].y);
        m.z = fmaxf(m.z, v[b].z); m.w = fmaxf(m.w, v[b].w);
    }
    float4 sum = make_float4(0.f, 0.f, 0.f, 0.f);
#pragma unroll
    for (int b = 0; b < B_SZ; ++b) {
        v[b].x = __expf(v[b].x - m.x); sum.x += v[b].x;
        v[b].y = __expf(v[b].y - m.y); sum.y += v[b].y;
        v[b].z = __expf(v[b].z - m.z); sum.z += v[b].z;
        v[b].w = __expf(v[b].w - m.w); sum.w += v[b].w;
    }
    sum.x = 1.f / sum.x; sum.y = 1.f / sum.y; sum.z = 1.f / sum.z; sum.w = 1.f / sum.w;
    const int base = s & ~31;
    const int p0 = (s & 31) >> 2;  // pos(s+e) = e*8 + p0
#pragma unroll
    for (int b = 0; b < B_SZ; ++b) {
        float* o = d + (size_t)b * plane + base + p0;
        o[0] = f2tf32f(v[b].x * sum.x);
        o[8] = f2tf32f(v[b].y * sum.y);
        o[16] = f2tf32f(v[b].z * sum.z);
        o[24] = f2tf32f(v[b].w * sum.w);
    }
}

// vT[b][h][perm(s)] = rna(v[b][s][h]).  32x32 tiles, block (32,8).
__global__ void transpose_rp(const float* __restrict__ v, float* __restrict__ vT)
{
    __shared__ float sm[32][33];
    const int b = blockIdx.z;
    const int h0 = blockIdx.x * 32;
    const int s0 = blockIdx.y * 32;
    const int tx = threadIdx.x, ty = threadIdx.y;
#pragma unroll
    for (int q = 0; q < 4; ++q)
        sm[ty + q * 8][tx] = v[((size_t)b * T_SZ + s0 + ty + q * 8) * HE_SZ + h0 + tx];
    __syncthreads();
    const int ps = (tx & 3) * 8 + (tx >> 2);  // pos(tx)
#pragma unroll
    for (int q = 0; q < 4; ++q)
        vT[(size_t)b * HE_SZ * T_SZ + (size_t)(h0 + ty + q * 8) * T_SZ + s0 + ps] =
            f2tf32f(sm[tx][ty + q * 8]);
}

extern "C" void kernel_launch(void* const* d_in, const int* in_sizes, int n_in,
                              void* d_out, int out_size)
{
    (void)in_sizes; (void)n_in; (void)out_size;
    const float* key   = (const float*)d_in[0];
    const float* value = (const float*)d_in[1];
    const float* query = (const float*)d_in[2];
    const float* Wk = (const float*)d_in[3];
    const float* bk = (const float*)d_in[4];
    const float* Wv = (const float*)d_in[5];
    const float* bv = (const float*)d_in[6];
    const float* Wq = (const float*)d_in[7];
    const float* bq = (const float*)d_in[8];
    const float* Wo = (const float*)d_in[9];
    const float* bo = (const float*)d_in[10];
    float* out = (float*)d_out;

    float *q, *k, *v, *vT, *att, *att2;
    float *rkey, *rqry, *rval, *rWk, *rWq, *rWv, *rWo;
    cudaGetSymbolAddress((void**)&q, g_q);
    cudaGetSymbolAddress((void**)&k, g_k);
    cudaGetSymbolAddress((void**)&v, g_v);
    cudaGetSymbolAddress((void**)&vT, g_vT);
    cudaGetSymbolAddress((void**)&att, g_att);
    cudaGetSymbolAddress((void**)&att2, g_att2);
    cudaGetSymbolAddress((void**)&rkey, g_rkey);
    cudaGetSymbolAddress((void**)&rqry, g_rqry);
    cudaGetSymbolAddress((void**)&rval, g_rval);
    cudaGetSymbolAddress((void**)&rWk, g_rWk);
    cudaGetSymbolAddress((void**)&rWq, g_rWq);
    cudaGetSymbolAddress((void**)&rWv, g_rWv);
    cudaGetSymbolAddress((void**)&rWo, g_rWo);

    cudaFuncSetAttribute((const void*)gemm_tf32<false, false>,
                         cudaFuncAttributeMaxDynamicSharedMemorySize, SMEM_BYTES);
    cudaFuncSetAttribute((const void*)gemm_tf32<false, true>,
                         cudaFuncAttributeMaxDynamicSharedMemorySize, SMEM_BYTES);
    cudaFuncSetAttribute((const void*)gemm_tf32<true, false>,
                         cudaFuncAttributeMaxDynamicSharedMemorySize, SMEM_BYTES);
    cudaFuncSetAttribute((const void*)gemm_tf32<true, true>,
                         cudaFuncAttributeMaxDynamicSharedMemorySize, SMEM_BYTES);

    const int MT = B_SZ * T_SZ;  // 16384
    const dim3 blk(256);

    // 0) round + permute all raw GEMM operands
    {
        const long long nin = (long long)MT * E_SZ / 4;      // 2M float4
        round_perm<<<(unsigned)((nin + 255) / 256), 256>>>(key, rkey, nin);
        round_perm<<<(unsigned)((nin + 255) / 256), 256>>>(query, rqry, nin);
        round_perm<<<(unsigned)((nin + 255) / 256), 256>>>(value, rval, nin);
        const long long nw = (long long)HE_SZ * E_SZ / 4;
        round_perm<<<(unsigned)((nw + 255) / 256), 256>>>(Wk, rWk, nw);
        round_perm<<<(unsigned)((nw + 255) / 256), 256>>>(Wq, rWq, nw);
        round_perm<<<(unsigned)((nw + 255) / 256), 256>>>(Wv, rWv, nw);
        round_perm<<<(unsigned)((nw + 255) / 256), 256>>>(Wo, rWo, nw);
    }
    // 1) projections: [16384,512] @ [4096,512]^T + bias
    {
        dim3 grid(HE_SZ / 128, MT / 128, 1);
        gemm_tf32<true, true><<<grid, blk, SMEM_BYTES>>>(rkey, rWk, bk, k, MT, HE_SZ, E_SZ, 1.f, 0, 0, 0);
        gemm_tf32<true, true><<<grid, blk, SMEM_BYTES>>>(rqry, rWq, bq, q, MT, HE_SZ, E_SZ, 1.f, 0, 0, 0);
        gemm_tf32<false, true><<<grid, blk, SMEM_BYTES>>>(rval, rWv, bv, v, MT, HE_SZ, E_SZ, 1.f, 0, 0, 0);
    }
    // 2) transpose v -> vT (rounded + permuted along s)
    {
        dim3 grid(HE_SZ / 32, T_SZ / 32, B_SZ);
        transpose_rp<<<grid, dim3(32, 8)>>>(v, vT);
    }
    // 3) logits: per batch [2048,4096] @ [2048,4096]^T * SCALE (plain out)
    {
        dim3 grid(T_SZ / 128, T_SZ / 128, B_SZ);
        const long long sqk = (long long)T_SZ * HE_SZ;
        const long long sp = (long long)T_SZ * T_SZ;
        gemm_tf32<false, false><<<grid, blk, SMEM_BYTES>>>(q, k, nullptr, att, T_SZ, T_SZ, HE_SZ,
                                                           SCALE_F, sqk, sqk, sp);
    }
    // 4) batch-axis softmax (rounded + permuted out)
    {
        const int plane = T_SZ * T_SZ;
        softmax_b8<<<(plane / 4) / 256, 256>>>(att, plane);
    }
    // 5) attend: per batch [2048,2048] @ ([4096,2048])^T -> att2 (perm out)
    {
        dim3 grid(HE_SZ / 128, T_SZ / 128, B_SZ);
        const long long sp = (long long)T_SZ * T_SZ;
        const long long sv = (long long)T_SZ * HE_SZ;
        gemm_tf32<true, false><<<grid, blk, SMEM_BYTES>>>(att, vT, nullptr, att2, T_SZ, HE_SZ, T_SZ,
                                                          1.f, sp, sv, sv);
    }
    // 6) output projection: [16384,4096] @ [512,4096]^T + bias (plain out)
    {
        dim3 grid(E_SZ / 128, MT / 128, 1);
        gemm_tf32<false, true><<<grid, blk, SMEM_BYTES>>>(att2, rWo, bo, out, MT, E_SZ, HE_SZ, 1.f, 0, 0, 0);
    }
}